// round 1
// baseline (speedup 1.0000x reference)
#include <cuda_runtime.h>
#include <stdint.h>

// Problem constants
constexpr int Fdim = 64;
constexpr int Rdim = 1024;
constexpr int Pdim = 128;
constexpr int Kdim = 257;   // [xa(64), xa^2(64), inter(128), 1]
constexpr int KPAD = 260;   // padded K (zeros in both operands)
constexpr int BM   = 64;    // batch rows per CTA
constexpr int BR   = 64;    // rules per chunk
constexpr int NTH  = 256;

#define LOG2E 1.4426950408889634f

// Scratch (device globals; no allocations allowed)
__device__ float  g_Ct[KPAD * Rdim];   // C transposed: [k][r], zero-padded k>=257
__device__ float4 g_kc[Rdim];          // -pp*sign*log2e       per (r,l)
__device__ float4 g_cc[Rdim];          //  pp*sign*th*log2e    per (r,l)
__device__ float4 g_mm[Rdim];          //  mask                per (r,l)

__device__ __forceinline__ float ex2f(float x) {
    float y; asm("ex2.approx.f32 %0, %1;" : "=f"(y) : "f"(x)); return y;
}
__device__ __forceinline__ float rcpf(float x) {
    float y; asm("rcp.approx.f32 %0, %1;" : "=f"(y) : "f"(x)); return y;
}

__global__ void prep_kernel(const float* __restrict__ C,    // [R][257]
                            const float* __restrict__ pp,   // [R]
                            const float* __restrict__ th,   // [R][4]
                            const float* __restrict__ sg,   // [R][4]
                            const float* __restrict__ mk)   // [R][4]
{
    int tid = blockIdx.x * blockDim.x + threadIdx.x;
    int nth = gridDim.x * blockDim.x;
    for (int i = tid; i < KPAD * Rdim; i += nth) {
        int k = i >> 10;          // / 1024
        int r = i & (Rdim - 1);
        g_Ct[i] = (k < Kdim) ? C[r * Kdim + k] : 0.0f;
    }
    for (int r = tid; r < Rdim; r += nth) {
        float s = pp[r];
        float kc[4], cc[4], mm[4];
        #pragma unroll
        for (int l = 0; l < 4; l++) {
            float sgn = sg[r * 4 + l];
            float t   = th[r * 4 + l];
            kc[l] = -s * sgn * LOG2E;
            cc[l] =  s * sgn * t * LOG2E;
            mm[l] = mk[r * 4 + l];
        }
        g_kc[r] = make_float4(kc[0], kc[1], kc[2], kc[3]);
        g_cc[r] = make_float4(cc[0], cc[1], cc[2], cc[3]);
        g_mm[r] = make_float4(mm[0], mm[1], mm[2], mm[3]);
    }
}

// Shared memory layout (floats):
//   sP  [KPAD][BM]   : 16640
//   sC  [KPAD][BR]   : 16640   (reused as reduction buffer at the end)
//   sXa [BM][65]     : 4160    (untransposed xa for firing gathers)
//   sAw [64]         : 64
//   sKc/sCc/sMm      : 3*256 (float4[64] each)
//   sId (int4[64])   : 256
constexpr int SM_P   = 0;
constexpr int SM_C   = SM_P + KPAD * BM;
constexpr int SM_XA  = SM_C + KPAD * BR;
constexpr int SM_AW  = SM_XA + BM * 65;
constexpr int SM_KC  = SM_AW + 64;
constexpr int SM_CC  = SM_KC + 256;
constexpr int SM_MM  = SM_CC + 256;
constexpr int SM_ID  = SM_MM + 256;
constexpr int SM_FLOATS = SM_ID + 256;
constexpr int SMEM_BYTES = SM_FLOATS * 4;   // 154112 bytes

__global__ __launch_bounds__(NTH, 1)
void anfis_kernel(const float* __restrict__ x,        // [B][64]
                  const float* __restrict__ aw,       // [64]
                  const int*   __restrict__ fidx,     // [R][4]
                  const int*   __restrict__ ipair,    // [P][2]
                  float*       __restrict__ out)      // [B]
{
    extern __shared__ float sm[];
    float* sP  = sm + SM_P;
    float* sC  = sm + SM_C;
    float* sXa = sm + SM_XA;
    float* sAw = sm + SM_AW;
    float4* sKc = (float4*)(sm + SM_KC);
    float4* sCc = (float4*)(sm + SM_CC);
    float4* sMm = (float4*)(sm + SM_MM);
    int4*   sId = (int4*)(sm + SM_ID);

    const int tid = threadIdx.x;
    const int b0  = blockIdx.x * BM;

    if (tid < 64) sAw[tid] = aw[tid];
    __syncthreads();

    // ---- Build xa, xa^2 into sP (k-major) and sXa (row-major) ----
    #pragma unroll
    for (int pass = 0; pass < 4; pass++) {
        int idx = tid + pass * NTH;        // 0..1023
        int b = idx >> 4;                  // 0..63
        int q = idx & 15;                  // float4 group along F
        float4 xv = *(const float4*)&x[(b0 + b) * Fdim + q * 4];
        float a0 = sAw[q * 4 + 0], a1 = sAw[q * 4 + 1];
        float a2 = sAw[q * 4 + 2], a3 = sAw[q * 4 + 3];
        float xa0 = xv.x * a0, xa1 = xv.y * a1, xa2 = xv.z * a2, xa3 = xv.w * a3;
        sXa[b * 65 + q * 4 + 0] = xa0;
        sXa[b * 65 + q * 4 + 1] = xa1;
        sXa[b * 65 + q * 4 + 2] = xa2;
        sXa[b * 65 + q * 4 + 3] = xa3;
        sP[(q * 4 + 0) * BM + b] = xa0;
        sP[(q * 4 + 1) * BM + b] = xa1;
        sP[(q * 4 + 2) * BM + b] = xa2;
        sP[(q * 4 + 3) * BM + b] = xa3;
        sP[(64 + q * 4 + 0) * BM + b] = xa0 * xa0;
        sP[(64 + q * 4 + 1) * BM + b] = xa1 * xa1;
        sP[(64 + q * 4 + 2) * BM + b] = xa2 * xa2;
        sP[(64 + q * 4 + 3) * BM + b] = xa3 * xa3;
    }
    __syncthreads();

    // ---- Interactions + ones + K padding ----
    {
        int b  = tid & 63;
        int pg = tid >> 6;   // 0..3
        for (int pi = pg; pi < Pdim; pi += 4) {
            int i0 = ipair[pi * 2 + 0];
            int i1 = ipair[pi * 2 + 1];
            float v = sXa[b * 65 + i0] * sXa[b * 65 + i1];
            sP[(128 + pi) * BM + b] = v;
        }
        if (pg == 0) {
            sP[256 * BM + b] = 1.0f;
            sP[257 * BM + b] = 0.0f;
            sP[258 * BM + b] = 0.0f;
            sP[259 * BM + b] = 0.0f;
        }
    }

    // ---- Main loop over rule chunks ----
    const int tc = tid & 15;   // r-group
    const int tr = tid >> 4;   // b-group
    const int rb = tr * 4;     // local batch row base
    const int cb = tc * 4;     // local rule col base

    float accY[4] = {0.f, 0.f, 0.f, 0.f};
    float accS[4] = {0.f, 0.f, 0.f, 0.f};

    for (int ch = 0; ch < Rdim / BR; ch++) {
        const int r0 = ch * BR;
        __syncthreads();  // previous chunk reads of sC done; also covers build on ch==0

        // Load C chunk (transposed source -> conflict-free float4 smem stores)
        for (int i = tid; i < KPAD * 16; i += NTH) {
            int k  = i >> 4;
            int rq = i & 15;
            float4 v = *(const float4*)&g_Ct[k * Rdim + r0 + rq * 4];
            *(float4*)&sC[k * BR + rq * 4] = v;
        }
        if (tid < 64) {
            sKc[tid] = g_kc[r0 + tid];
            sCc[tid] = g_cc[r0 + tid];
            sMm[tid] = g_mm[r0 + tid];
            sId[tid] = *(const int4*)&fidx[(r0 + tid) * 4];
        }
        __syncthreads();

        // GEMM micro-tile: D[4][4] over K
        float D[4][4] = {{0.f}};
        #pragma unroll 4
        for (int k = 0; k < KPAD; k++) {
            float4 av = *(const float4*)(sP + k * BM + rb);
            float4 bv = *(const float4*)(sC + k * BR + cb);
            float a[4] = {av.x, av.y, av.z, av.w};
            float c[4] = {bv.x, bv.y, bv.z, bv.w};
            #pragma unroll
            for (int i = 0; i < 4; i++)
                #pragma unroll
                for (int j = 0; j < 4; j++)
                    D[i][j] = fmaf(a[i], c[j], D[i][j]);
        }

        // Firing + fused epilogue: firing = 1 / prod(1 + m * exp(-z))
        #pragma unroll
        for (int j = 0; j < 4; j++) {
            float4 kc = sKc[cb + j];
            float4 cc = sCc[cb + j];
            float4 mm = sMm[cb + j];
            int4   id = sId[cb + j];
            #pragma unroll
            for (int i = 0; i < 4; i++) {
                const float* xr = sXa + (rb + i) * 65;
                float u0 = ex2f(fmaf(kc.x, xr[id.x], cc.x));
                float u1 = ex2f(fmaf(kc.y, xr[id.y], cc.y));
                float u2 = ex2f(fmaf(kc.z, xr[id.z], cc.z));
                float u3 = ex2f(fmaf(kc.w, xr[id.w], cc.w));
                float fac = fmaf(mm.x, u0, 1.0f) * fmaf(mm.y, u1, 1.0f)
                          * fmaf(mm.z, u2, 1.0f) * fmaf(mm.w, u3, 1.0f);
                float f = rcpf(fac);
                accS[i] += f;
                accY[i] = fmaf(f, D[i][j], accY[i]);
            }
        }
    }

    // ---- Cross-thread reduction over the 16 rule-column groups ----
    __syncthreads();
    float* redY = sC;             // [64][16]
    float* redS = sC + 64 * 16;   // [64][16]
    #pragma unroll
    for (int i = 0; i < 4; i++) {
        redY[(rb + i) * 16 + tc] = accY[i];
        redS[(rb + i) * 16 + tc] = accS[i];
    }
    __syncthreads();
    if (tid < 64) {
        float sy = 0.f, ss = 0.f;
        #pragma unroll
        for (int t = 0; t < 16; t++) {
            sy += redY[tid * 16 + t];
            ss += redS[tid * 16 + t];
        }
        out[b0 + tid] = sy / (ss + 1e-8f);
    }
}

extern "C" void kernel_launch(void* const* d_in, const int* in_sizes, int n_in,
                              void* d_out, int out_size)
{
    const float* x    = (const float*)d_in[0];   // [16384,64]
    const float* aw   = (const float*)d_in[1];   // [64]
    const float* pp   = (const float*)d_in[2];   // [1024]
    const float* th   = (const float*)d_in[3];   // [1024,4]
    const float* sg   = (const float*)d_in[4];   // [1024,4]
    const float* mk   = (const float*)d_in[5];   // [1024,4]
    const float* C    = (const float*)d_in[6];   // [1024,257]
    const int*   fid  = (const int*)  d_in[7];   // [1024,4]
    const int*   ip   = (const int*)  d_in[8];   // [128,2]
    float* out = (float*)d_out;

    cudaFuncSetAttribute(anfis_kernel,
                         cudaFuncAttributeMaxDynamicSharedMemorySize,
                         SMEM_BYTES);

    prep_kernel<<<64, 256>>>(C, pp, th, sg, mk);
    anfis_kernel<<<16384 / BM, NTH, SMEM_BYTES>>>(x, aw, fid, ip, out);
}

// round 2
// speedup vs baseline: 2.5697x; 2.5697x over previous
#include <cuda_runtime.h>
#include <stdint.h>

// Problem constants
constexpr int Fdim = 64;
constexpr int Rdim = 1024;
constexpr int Pdim = 128;
constexpr int Kdim = 257;   // [xa(64), xa^2(64), inter(128), 1]
constexpr int KPAD = 264;   // padded K, multiple of 4*66
constexpr int BM   = 128;   // batch rows per CTA
constexpr int BR   = 128;   // rules per chunk
constexpr int NTH  = 256;
constexpr int KQ   = 66;    // k-quarter size
constexpr int NQ   = 4;     // quarters per chunk
constexpr int PSTR = 132;   // padded row stride of sP (banks: (4*id+b)&31 spreads gathers)
constexpr int NCH  = Rdim / BR;   // 8 rule chunks

#define LOG2E 1.4426950408889634f

// Device-global scratch (no allocations allowed)
__device__ float  g_Ct[KPAD * Rdim];   // C transposed: [k][r], zero-padded k>=257
__device__ float4 g_kc[Rdim];          // -pp*sign*log2e     per (r,l)
__device__ float4 g_cc[Rdim];          //  pp*sign*th*log2e  per (r,l)
__device__ float4 g_mm[Rdim];          //  mask              per (r,l)

__device__ __forceinline__ float ex2f(float x) {
    float y; asm("ex2.approx.f32 %0, %1;" : "=f"(y) : "f"(x)); return y;
}
__device__ __forceinline__ float rcpf(float x) {
    float y; asm("rcp.approx.f32 %0, %1;" : "=f"(y) : "f"(x)); return y;
}
__device__ __forceinline__ unsigned long long pack2(float lo, float hi) {
    unsigned long long r;
    asm("mov.b64 %0, {%1, %2};" : "=l"(r)
        : "r"(__float_as_uint(lo)), "r"(__float_as_uint(hi)));
    return r;
}
__device__ __forceinline__ void unpack2(unsigned long long v, float& lo, float& hi) {
    unsigned int a, b;
    asm("mov.b64 {%0, %1}, %2;" : "=r"(a), "=r"(b) : "l"(v));
    lo = __uint_as_float(a); hi = __uint_as_float(b);
}
__device__ __forceinline__ unsigned long long ffma2(unsigned long long a,
                                                    unsigned long long b,
                                                    unsigned long long c) {
    unsigned long long d;
    asm("fma.rn.f32x2 %0, %1, %2, %3;" : "=l"(d) : "l"(a), "l"(b), "l"(c));
    return d;
}

__global__ void prep_kernel(const float* __restrict__ C,    // [R][257]
                            const float* __restrict__ pp,   // [R]
                            const float* __restrict__ th,   // [R][4]
                            const float* __restrict__ sg,   // [R][4]
                            const float* __restrict__ mk)   // [R][4]
{
    int tid = blockIdx.x * blockDim.x + threadIdx.x;
    int nth = gridDim.x * blockDim.x;
    for (int i = tid; i < KPAD * Rdim; i += nth) {
        int k = i >> 10;
        int r = i & (Rdim - 1);
        g_Ct[i] = (k < Kdim) ? C[r * Kdim + k] : 0.0f;
    }
    for (int r = tid; r < Rdim; r += nth) {
        float s = pp[r];
        float kc[4], cc[4], mm[4];
        #pragma unroll
        for (int l = 0; l < 4; l++) {
            float sgn = sg[r * 4 + l];
            float t   = th[r * 4 + l];
            kc[l] = -s * sgn * LOG2E;
            cc[l] =  s * sgn * t * LOG2E;
            mm[l] = mk[r * 4 + l];
        }
        g_kc[r] = make_float4(kc[0], kc[1], kc[2], kc[3]);
        g_cc[r] = make_float4(cc[0], cc[1], cc[2], cc[3]);
        g_mm[r] = make_float4(mm[0], mm[1], mm[2], mm[3]);
    }
}

// Shared memory (floats):
//   sP [KPAD][PSTR] : 264*132 = 34848   (k-major P tile; rows 0..63 double as xa for gathers)
//   sC [2][KQ][BR]  : 2*66*128 = 16896  (double-buffered C k-quarters; reused for reduction)
constexpr int SM_P = 0;
constexpr int SM_C = KPAD * PSTR;
constexpr int SM_FLOATS = SM_C + 2 * KQ * BR;
constexpr int SMEM_BYTES = SM_FLOATS * 4;   // 206976 bytes

__global__ __launch_bounds__(NTH, 1)
void anfis_kernel(const float* __restrict__ x,        // [B][64]
                  const float* __restrict__ aw,       // [64]
                  const int*   __restrict__ fidx,     // [R][4]
                  const int*   __restrict__ ipair,    // [P][2]
                  float*       __restrict__ out)      // [B]
{
    extern __shared__ float sm[];
    const int tid = threadIdx.x;
    const int b0  = blockIdx.x * BM;

    const uint32_t smem_u32 = (uint32_t)__cvta_generic_to_shared(sm);
    const uint32_t smPu = smem_u32;
    const uint32_t smCu = smem_u32 + SM_C * 4;

    // ---- Build P tile: xa (rows 0..63), xa^2 (64..127) ----
    #pragma unroll
    for (int pass = 0; pass < 8; pass++) {
        int idx = tid + pass * NTH;        // 0..2047
        int b = idx >> 4;                  // 0..127
        int q = idx & 15;                  // float4 group along F
        float4 xv = *(const float4*)&x[(b0 + b) * Fdim + q * 4];
        float4 av = __ldg((const float4*)aw + q);
        float xa0 = xv.x * av.x, xa1 = xv.y * av.y;
        float xa2 = xv.z * av.z, xa3 = xv.w * av.w;
        sm[(q * 4 + 0) * PSTR + b] = xa0;
        sm[(q * 4 + 1) * PSTR + b] = xa1;
        sm[(q * 4 + 2) * PSTR + b] = xa2;
        sm[(q * 4 + 3) * PSTR + b] = xa3;
        sm[(64 + q * 4 + 0) * PSTR + b] = xa0 * xa0;
        sm[(64 + q * 4 + 1) * PSTR + b] = xa1 * xa1;
        sm[(64 + q * 4 + 2) * PSTR + b] = xa2 * xa2;
        sm[(64 + q * 4 + 3) * PSTR + b] = xa3 * xa3;
    }
    __syncthreads();

    // ---- Interactions (rows 128..255), ones (256), pad (257..263) ----
    {
        int b  = tid & 127;
        int pg = tid >> 7;   // 0..1
        for (int pi = pg; pi < Pdim; pi += 2) {
            int2 pr = __ldg((const int2*)ipair + pi);
            float v = sm[pr.x * PSTR + b] * sm[pr.y * PSTR + b];
            sm[(128 + pi) * PSTR + b] = v;
        }
        if (pg == 0) {
            sm[256 * PSTR + b] = 1.0f;
            #pragma unroll
            for (int rr = 257; rr < KPAD; rr++) sm[rr * PSTR + b] = 0.0f;
        }
    }
    __syncthreads();

    // ---- cp.async quarter loader ----
    auto issue_quarter = [&](int bbuf, int ch2, int kq2) {
        const float* src_base = g_Ct + (kq2 * KQ) * Rdim + ch2 * BR;
        uint32_t dst_base = smCu + (bbuf * KQ * BR) * 4;
        for (int i = tid; i < KQ * (BR / 4); i += NTH) {
            int kk = i >> 5;        // BR/4 = 32
            int c4 = i & 31;
            uint32_t dst = dst_base + (uint32_t)(kk * BR + c4 * 4) * 4;
            const float* src = src_base + kk * Rdim + c4 * 4;
            asm volatile("cp.async.cg.shared.global [%0], [%1], 16;"
                         :: "r"(dst), "l"(src) : "memory");
        }
        asm volatile("cp.async.commit_group;" ::: "memory");
    };

    const int tc = tid & 15;   // rule-col group
    const int tr = tid >> 4;   // row group
    const int rb = tr * 8;
    const int cb = tc * 8;

    float accY[8], accS[8];
    #pragma unroll
    for (int i = 0; i < 8; i++) { accY[i] = 0.f; accS[i] = 0.f; }

    issue_quarter(0, 0, 0);
    int buf = 0;

    for (int ch = 0; ch < NCH; ch++) {
        unsigned long long D2[4][8];
        #pragma unroll
        for (int i = 0; i < 4; i++)
            #pragma unroll
            for (int j = 0; j < 8; j++) D2[i][j] = 0ULL;

        for (int kq = 0; kq < NQ; kq++) {
            int nch = ch, nkq = kq + 1;
            if (nkq == NQ) { nkq = 0; nch++; }
            if (nch < NCH) {
                issue_quarter(buf ^ 1, nch, nkq);
                asm volatile("cp.async.wait_group 1;" ::: "memory");
            } else {
                asm volatile("cp.async.wait_group 0;" ::: "memory");
            }
            __syncthreads();

            uint32_t aAddr = smPu + (uint32_t)((kq * KQ) * PSTR + rb) * 4;
            uint32_t cAddr = smCu + (uint32_t)(buf * KQ * BR + cb) * 4;

            #pragma unroll 6
            for (int kk = 0; kk < KQ; kk++) {
                unsigned long long a0, a1, a2, a3;
                asm("ld.shared.v2.b64 {%0,%1}, [%2];"
                    : "=l"(a0), "=l"(a1) : "r"(aAddr));
                asm("ld.shared.v2.b64 {%0,%1}, [%2];"
                    : "=l"(a2), "=l"(a3) : "r"(aAddr + 16));
                float c0, c1, c2, c3, c4, c5, c6, c7;
                asm("ld.shared.v4.f32 {%0,%1,%2,%3}, [%4];"
                    : "=f"(c0), "=f"(c1), "=f"(c2), "=f"(c3) : "r"(cAddr));
                asm("ld.shared.v4.f32 {%0,%1,%2,%3}, [%4];"
                    : "=f"(c4), "=f"(c5), "=f"(c6), "=f"(c7) : "r"(cAddr + 16));

                unsigned long long cd;
                #define STEP(J, CV)                                    \
                    cd = pack2(CV, CV);                                \
                    D2[0][J] = ffma2(a0, cd, D2[0][J]);                \
                    D2[1][J] = ffma2(a1, cd, D2[1][J]);                \
                    D2[2][J] = ffma2(a2, cd, D2[2][J]);                \
                    D2[3][J] = ffma2(a3, cd, D2[3][J]);
                STEP(0, c0) STEP(1, c1) STEP(2, c2) STEP(3, c3)
                STEP(4, c4) STEP(5, c5) STEP(6, c6) STEP(7, c7)
                #undef STEP

                aAddr += PSTR * 4;
                cAddr += BR * 4;
            }
            __syncthreads();
            buf ^= 1;
        }

        // ---- Fused epilogue: firing = 1 / prod(1 + m * exp(-z)) ----
        float D[8][8];
        #pragma unroll
        for (int i2 = 0; i2 < 4; i2++)
            #pragma unroll
            for (int j = 0; j < 8; j++)
                unpack2(D2[i2][j], D[2 * i2][j], D[2 * i2 + 1][j]);

        const int r0 = ch * BR;
        #pragma unroll
        for (int j = 0; j < 8; j++) {
            int r = r0 + cb + j;
            float4 kc = __ldg(&g_kc[r]);
            float4 cc = __ldg(&g_cc[r]);
            float4 mm = __ldg(&g_mm[r]);
            int4   id = __ldg((const int4*)fidx + r);
            const float* x0 = sm + id.x * PSTR + rb;
            const float* x1 = sm + id.y * PSTR + rb;
            const float* x2 = sm + id.z * PSTR + rb;
            const float* x3 = sm + id.w * PSTR + rb;
            #pragma unroll
            for (int i = 0; i < 8; i++) {
                float u0 = ex2f(fmaf(kc.x, x0[i], cc.x));
                float u1 = ex2f(fmaf(kc.y, x1[i], cc.y));
                float u2 = ex2f(fmaf(kc.z, x2[i], cc.z));
                float u3 = ex2f(fmaf(kc.w, x3[i], cc.w));
                float fac = fmaf(mm.x, u0, 1.0f) * fmaf(mm.y, u1, 1.0f)
                          * fmaf(mm.z, u2, 1.0f) * fmaf(mm.w, u3, 1.0f);
                float f = rcpf(fac);
                accS[i] += f;
                accY[i] = fmaf(f, D[i][j], accY[i]);
            }
        }
    }

    // ---- Cross-thread reduction over the 16 rule-col groups ----
    __syncthreads();
    float* redY = sm + SM_C;              // [128][16]
    float* redS = sm + SM_C + BM * 16;    // [128][16]
    #pragma unroll
    for (int i = 0; i < 8; i++) {
        redY[(rb + i) * 16 + tc] = accY[i];
        redS[(rb + i) * 16 + tc] = accS[i];
    }
    __syncthreads();
    if (tid < BM) {
        float sy = 0.f, ss = 0.f;
        #pragma unroll
        for (int t = 0; t < 16; t++) {
            sy += redY[tid * 16 + t];
            ss += redS[tid * 16 + t];
        }
        out[b0 + tid] = sy / (ss + 1e-8f);
    }
}

extern "C" void kernel_launch(void* const* d_in, const int* in_sizes, int n_in,
                              void* d_out, int out_size)
{
    const float* x    = (const float*)d_in[0];   // [16384,64]
    const float* aw   = (const float*)d_in[1];   // [64]
    const float* pp   = (const float*)d_in[2];   // [1024]
    const float* th   = (const float*)d_in[3];   // [1024,4]
    const float* sg   = (const float*)d_in[4];   // [1024,4]
    const float* mk   = (const float*)d_in[5];   // [1024,4]
    const float* C    = (const float*)d_in[6];   // [1024,257]
    const int*   fid  = (const int*)  d_in[7];   // [1024,4]
    const int*   ip   = (const int*)  d_in[8];   // [128,2]
    float* out = (float*)d_out;

    cudaFuncSetAttribute(anfis_kernel,
                         cudaFuncAttributeMaxDynamicSharedMemorySize,
                         SMEM_BYTES);

    prep_kernel<<<64, 256>>>(C, pp, th, sg, mk);
    anfis_kernel<<<16384 / BM, NTH, SMEM_BYTES>>>(x, aw, fid, ip, out);
}

// round 4
// speedup vs baseline: 6.8790x; 2.6769x over previous
#include <cuda_runtime.h>
#include <stdint.h>

// Problem constants
constexpr int Fdim = 64;
constexpr int Rdim = 1024;
constexpr int Pdim = 128;
constexpr int BM   = 128;           // batch rows per CTA
constexpr int NCR  = 256;           // rules per chunk
constexpr int NCH  = Rdim / NCR;    // 4 chunks
constexpr int K8   = 33;            // k8 tiles (K padded to 264)
constexpr int QK8  = 3;             // k8 tiles per quarter-step
constexpr int NQ   = 11;            // quarter-steps per chunk
constexpr int NSTEP = NCH * NQ;     // 44
constexpr int NTH  = 256;
constexpr int STEP_FLOATS = (NCR / 8) * QK8 * 32 * 2;   // 6144
constexpr int STEP_BYTES  = STEP_FLOATS * 4;            // 24576

#define LOG2E 1.4426950408889634f

// ---- Device-global scratch ----
__device__ uint32_t g_Bf[NSTEP * STEP_FLOATS];  // B in mma-fragment order, tf32
__device__ float4   g_kc[Rdim];                 // -pp*sign*log2e
__device__ float4   g_cc[Rdim];                 //  pp*sign*th*log2e
__device__ float4   g_mm[Rdim];                 //  mask

__device__ __forceinline__ float ex2f(float x) {
    float y; asm("ex2.approx.f32 %0, %1;" : "=f"(y) : "f"(x)); return y;
}
__device__ __forceinline__ float rcpf(float x) {
    float y; asm("rcp.approx.f32 %0, %1;" : "=f"(y) : "f"(x)); return y;
}
__device__ __forceinline__ uint32_t to_tf32(float f) {
    uint32_t r; asm("cvt.rna.tf32.f32 %0, %1;" : "=r"(r) : "f"(f)); return r;
}

// A fragment slot (float index) for logical element (row, k).
// m16n8k8 A frag: a0=(g,tig) a1=(g+8,tig) a2=(g,tig+4) a3=(g+8,tig+4), lane=g*4+tig
__device__ __forceinline__ int afrag_idx(int row, int k) {
    int m = row >> 4, g = row & 7, hi = (row >> 3) & 1;
    int k8 = k >> 3, tig = k & 3, khi = (k >> 2) & 1;
    return ((m * K8 + k8) * 32 + g * 4 + tig) * 4 + (hi + 2 * khi);
}

__global__ void prep_kernel(const float* __restrict__ C,    // [R][257]
                            const float* __restrict__ pp,   // [R]
                            const float* __restrict__ th,   // [R][4]
                            const float* __restrict__ sg,   // [R][4]
                            const float* __restrict__ mk)   // [R][4]
{
    int t = blockIdx.x * blockDim.x + threadIdx.x;
    // B-fragment arrangement: one (r, k8) item per thread, 8 values = 32B store
    if (t < Rdim * K8) {
        int r  = t / K8;
        int k8 = t - r * K8;
        int chunk = r >> 8, rl = r & 255;
        int nt = rl >> 3, nn = rl & 7;
        int q = k8 / QK8, k8q = k8 - q * QK8;
        int base = (chunk * NQ + q) * STEP_FLOATS
                 + ((nt * QK8 + k8q) * 32 + nn * 4) * 2;
        uint32_t v[8];
        #pragma unroll
        for (int p = 0; p < 8; p++) {
            int kk = (p & 1) * 4 + (p >> 1);   // mem pos p = tig*2 + khi
            int k = k8 * 8 + kk;
            float f = (k < 257) ? C[r * 257 + k] : 0.0f;
            v[p] = to_tf32(f);
        }
        uint4* dst = (uint4*)&g_Bf[base];
        dst[0] = make_uint4(v[0], v[1], v[2], v[3]);
        dst[1] = make_uint4(v[4], v[5], v[6], v[7]);
    }
    if (t < Rdim) {
        float s = pp[t];
        float kc[4], cc[4], mm[4];
        #pragma unroll
        for (int l = 0; l < 4; l++) {
            float sgn = sg[t * 4 + l];
            float tt  = th[t * 4 + l];
            kc[l] = -s * sgn * LOG2E;
            cc[l] =  s * sgn * tt * LOG2E;
            mm[l] = mk[t * 4 + l];
        }
        g_kc[t] = make_float4(kc[0], kc[1], kc[2], kc[3]);
        g_cc[t] = make_float4(cc[0], cc[1], cc[2], cc[3]);
        g_mm[t] = make_float4(mm[0], mm[1], mm[2], mm[3]);
    }
}

// ---- Shared memory layout (bytes) ----
constexpr int SMA  = 0;                       // A frags: 33792 u32 = 135168 B
constexpr int SMB  = 135168;                  // B double buffer: 2*24576 = 49152 B
constexpr int SMXA = 184320;                  // sXa: 64 x 132 f32 = 33792 B
constexpr int SMEM_BYTES = 218112;

__global__ __launch_bounds__(NTH, 1)
void anfis_kernel(const float* __restrict__ x,        // [B][64]
                  const float* __restrict__ aw,       // [64]
                  const int*   __restrict__ fidx,     // [R][4]
                  const int*   __restrict__ ipair,    // [P][2]
                  float*       __restrict__ out)      // [B]
{
    extern __shared__ char smem[];
    const int tid  = threadIdx.x;
    const int wid  = tid >> 5;
    const int lane = tid & 31;
    const int g    = lane >> 2;
    const int tig  = lane & 3;
    const int wr   = wid >> 1;   // 0..3 : row group (32 rows)
    const int wc   = wid & 1;    // 0..1 : col group (128 rules)
    const int b0   = blockIdx.x * BM;

    uint32_t* sA  = (uint32_t*)smem;
    float*    sXa = (float*)(smem + SMXA);
    const uint32_t smu  = (uint32_t)__cvta_generic_to_shared(smem);
    const uint32_t smAu = smu + SMA;
    const uint32_t smBu = smu + SMB;

    // ---- Prologue: build A fragments (tf32) + sXa (f32) ----
    #pragma unroll
    for (int pass = 0; pass < 8; pass++) {
        int idx = tid + pass * NTH;     // 0..2047
        int b = idx >> 4;
        int q = idx & 15;
        int f = q * 4;
        float4 xv = *(const float4*)&x[(b0 + b) * Fdim + f];
        float4 av = __ldg((const float4*)aw + q);
        float xa[4] = {xv.x * av.x, xv.y * av.y, xv.z * av.z, xv.w * av.w};
        #pragma unroll
        for (int j = 0; j < 4; j++) {
            sA[afrag_idx(b, f + j)]      = to_tf32(xa[j]);
            sA[afrag_idx(b, 64 + f + j)] = to_tf32(xa[j] * xa[j]);
            sXa[(f + j) * 132 + b] = xa[j];
        }
    }
    __syncthreads();
    {
        int b  = tid & 127;
        int pg = tid >> 7;
        for (int pi = pg; pi < Pdim; pi += 2) {
            int2 pr = __ldg((const int2*)ipair + pi);
            float v = sXa[pr.x * 132 + b] * sXa[pr.y * 132 + b];
            sA[afrag_idx(b, 128 + pi)] = to_tf32(v);
        }
        if (pg == 0) {
            sA[afrag_idx(b, 256)] = to_tf32(1.0f);
            #pragma unroll
            for (int k = 257; k < 264; k++) sA[afrag_idx(b, k)] = 0u;
        }
    }
    __syncthreads();

    // ---- B streamer (all threads): one step = 24576 B ----
    auto issue = [&](int step) {
        const char* src = (const char*)g_Bf + (size_t)step * STEP_BYTES;
        uint32_t dst = smBu + (uint32_t)(step & 1) * STEP_BYTES;
        #pragma unroll
        for (int i = 0; i < 6; i++) {
            asm volatile("cp.async.cg.shared.global [%0], [%1], 16;"
                         :: "r"(dst + (tid + i * NTH) * 16),
                            "l"(src + (tid + i * NTH) * 16) : "memory");
        }
        asm volatile("cp.async.commit_group;" ::: "memory");
    };

    float accY[4] = {0.f, 0.f, 0.f, 0.f};
    float accS[4] = {0.f, 0.f, 0.f, 0.f};

    issue(0);

    for (int chunk = 0; chunk < NCH; chunk++) {
        float d[2][16][4];
        #pragma unroll
        for (int mi = 0; mi < 2; mi++)
            #pragma unroll
            for (int nt = 0; nt < 16; nt++)
                #pragma unroll
                for (int rr = 0; rr < 4; rr++) d[mi][nt][rr] = 0.f;

        for (int qq = 0; qq < NQ; qq++) {
            int step = chunk * NQ + qq;
            if (step + 1 < NSTEP) {
                issue(step + 1);
                asm volatile("cp.async.wait_group 1;" ::: "memory");
            } else {
                asm volatile("cp.async.wait_group 0;" ::: "memory");
            }
            __syncthreads();

            uint32_t bufb = smBu + (uint32_t)(step & 1) * STEP_BYTES;

            #pragma unroll
            for (int k8q = 0; k8q < QK8; k8q++) {
                int k8 = qq * QK8 + k8q;
                uint32_t a[2][4];
                #pragma unroll
                for (int mi = 0; mi < 2; mi++) {
                    uint32_t aAddr = smAu +
                        (uint32_t)((((wr * 2 + mi) * K8 + k8) * 32 + lane) * 16);
                    asm("ld.shared.v4.b32 {%0,%1,%2,%3}, [%4];"
                        : "=r"(a[mi][0]), "=r"(a[mi][1]),
                          "=r"(a[mi][2]), "=r"(a[mi][3]) : "r"(aAddr));
                }
                uint32_t bfr[16][2];
                #pragma unroll
                for (int nt = 0; nt < 16; nt++) {
                    uint32_t bAddr = bufb +
                        (uint32_t)((((wc * 16 + nt) * QK8 + k8q) * 32 + lane) * 8);
                    asm("ld.shared.v2.b32 {%0,%1}, [%2];"
                        : "=r"(bfr[nt][0]), "=r"(bfr[nt][1]) : "r"(bAddr));
                }
                #pragma unroll
                for (int mi = 0; mi < 2; mi++)
                    #pragma unroll
                    for (int nt = 0; nt < 16; nt++) {
                        asm("mma.sync.aligned.m16n8k8.row.col.f32.tf32.tf32.f32 "
                            "{%0,%1,%2,%3}, {%4,%5,%6,%7}, {%8,%9}, {%0,%1,%2,%3};"
                            : "+f"(d[mi][nt][0]), "+f"(d[mi][nt][1]),
                              "+f"(d[mi][nt][2]), "+f"(d[mi][nt][3])
                            : "r"(a[mi][0]), "r"(a[mi][1]),
                              "r"(a[mi][2]), "r"(a[mi][3]),
                              "r"(bfr[nt][0]), "r"(bfr[nt][1]));
                    }
            }
            __syncthreads();
        }

        // ---- Fused epilogue: firing = 1 / prod(1 + m*exp(-z)) ----
        #pragma unroll
        for (int nt = 0; nt < 16; nt++) {
            #pragma unroll
            for (int ccc = 0; ccc < 2; ccc++) {
                int r = chunk * NCR + (wc * 16 + nt) * 8 + tig * 2 + ccc;
                float4 kc = __ldg(&g_kc[r]);
                float4 cc = __ldg(&g_cc[r]);
                float4 mm = __ldg(&g_mm[r]);
                int4   id = __ldg((const int4*)fidx + r);
                const float* x0 = sXa + id.x * 132;
                const float* x1 = sXa + id.y * 132;
                const float* x2 = sXa + id.z * 132;
                const float* x3 = sXa + id.w * 132;
                #pragma unroll
                for (int mi = 0; mi < 2; mi++) {
                    #pragma unroll
                    for (int hi = 0; hi < 2; hi++) {
                        int row = wr * 32 + mi * 16 + hi * 8 + g;
                        float u0 = ex2f(fmaf(kc.x, x0[row], cc.x));
                        float u1 = ex2f(fmaf(kc.y, x1[row], cc.y));
                        float u2 = ex2f(fmaf(kc.z, x2[row], cc.z));
                        float u3 = ex2f(fmaf(kc.w, x3[row], cc.w));
                        float fac = fmaf(mm.x, u0, 1.0f) * fmaf(mm.y, u1, 1.0f)
                                  * fmaf(mm.z, u2, 1.0f) * fmaf(mm.w, u3, 1.0f);
                        float f = rcpf(fac);
                        accS[mi * 2 + hi] += f;
                        accY[mi * 2 + hi] =
                            fmaf(f, d[mi][nt][hi * 2 + ccc], accY[mi * 2 + hi]);
                    }
                }
            }
        }
    }

    // ---- Reduce: shuffle over tig (4 lanes), then smem over wc (2 warps) ----
    #pragma unroll
    for (int s = 1; s <= 2; s <<= 1) {
        #pragma unroll
        for (int i = 0; i < 4; i++) {
            accY[i] += __shfl_xor_sync(0xffffffff, accY[i], s);
            accS[i] += __shfl_xor_sync(0xffffffff, accS[i], s);
        }
    }
    float* redY = (float*)(smem + SMB);        // [128][2]
    float* redS = redY + 256;
    if (tig == 0) {
        #pragma unroll
        for (int i = 0; i < 4; i++) {
            int row = wr * 32 + (i >> 1) * 16 + (i & 1) * 8 + g;
            redY[row * 2 + wc] = accY[i];
            redS[row * 2 + wc] = accS[i];
        }
    }
    __syncthreads();
    if (tid < BM) {
        float sy = redY[tid * 2] + redY[tid * 2 + 1];
        float ss = redS[tid * 2] + redS[tid * 2 + 1];
        out[b0 + tid] = sy / (ss + 1e-8f);
    }
}

extern "C" void kernel_launch(void* const* d_in, const int* in_sizes, int n_in,
                              void* d_out, int out_size)
{
    const float* x    = (const float*)d_in[0];   // [16384,64]
    const float* aw   = (const float*)d_in[1];   // [64]
    const float* pp   = (const float*)d_in[2];   // [1024]
    const float* th   = (const float*)d_in[3];   // [1024,4]
    const float* sg   = (const float*)d_in[4];   // [1024,4]
    const float* mk   = (const float*)d_in[5];   // [1024,4]
    const float* C    = (const float*)d_in[6];   // [1024,257]
    const int*   fid  = (const int*)  d_in[7];   // [1024,4]
    const int*   ip   = (const int*)  d_in[8];   // [128,2]
    float* out = (float*)d_out;

    cudaFuncSetAttribute(anfis_kernel,
                         cudaFuncAttributeMaxDynamicSharedMemorySize,
                         SMEM_BYTES);

    prep_kernel<<<132, 256>>>(C, pp, th, sg, mk);
    anfis_kernel<<<16384 / BM, NTH, SMEM_BYTES>>>(x, aw, fid, ip, out);
}